// round 10
// baseline (speedup 1.0000x reference)
#include <cuda_runtime.h>

#define BINS  10
#define BLOCK 256
#define OCC   4
#define GRID  (148 * OCC)

// Global scratch (zero at module load; reset by last block each run -> graph-replayable).
__device__ float    g_sum[BINS];
__device__ float    g_cnt[BINS];
__device__ unsigned g_ticket;

#define LOG2E 1.4426950408889634f
#define LN2   0.69314718055994531f

__device__ __forceinline__ float rcp_approx(float p) {
    float r;
    asm("rcp.approx.f32 %0, %1;" : "=f"(r) : "f"(p));   // single MUFU.RCP
    return r;
}
__device__ __forceinline__ unsigned long long pack2(float lo, float hi) {
    unsigned long long v;
    asm("mov.b64 %0, {%1, %2};" : "=l"(v) : "f"(lo), "f"(hi));
    return v;
}

// rowbase = (char*)rows + tid*8 ; cell for bin b at rowbase + b*2048 (conflict-free:
// bank-pair = tid mod 16, bin term moves whole 32-bank rows).
__device__ __forceinline__ void ghm_elem(float xx, int tt, char* __restrict__ rowbase) {
    // z = x if t==0 else -x. Adding t<<31 flips only the sign bit -> 1 LEA.
    const int   zi = __float_as_int(xx) + (int)(((unsigned)tt) << 31);
    const float z  = __int_as_float(zi);
    const float a  = exp2f(z * LOG2E);            // e^z        (FMUL + MUFU.EX2)
    const float p  = 1.0f + a;                    // 1 + e^z    (inf-safe)
    const float l  = __log2f(p);                  // MUFU.LG2: ce = ln2 * l (scaled at finalize)
    const float r  = rcp_approx(p);               // MUFU.RCP (approx): sigmoid(z) = 1 - r
    const float g9 = 9.9999f - 9.9999f * r;       // FFMA: g*(BINS-1e-4) in [0, 9.9999)
    const int  bin = (int)g9;                     // F2I trunc; p=inf -> r=0 -> bin 9
    unsigned long long* cell = (unsigned long long*)(rowbase + (bin << 11));
    const unsigned long long inc = pack2(l, 1.0f);
    unsigned long long v = *cell;                               // LDS.64
    asm("add.rn.f32x2 %0, %0, %1;" : "+l"(v) : "l"(inc));       // packed (sum, cnt) add
    *cell = v;                                                  // STS.64
}

__global__ void __launch_bounds__(BLOCK, OCC)
ghm_fused(const float* __restrict__ x, const int* __restrict__ tg, int n,
          float* __restrict__ out, int out_size) {
    __shared__ float2 rows[BINS][BLOCK];   // [bin][tid]
    __shared__ float  sh_fin[2 * BINS];
    __shared__ bool   s_last;

    const int tid = threadIdx.x;
    char* __restrict__ rowbase = (char*)rows + tid * (int)sizeof(float2);
    #pragma unroll
    for (int b = 0; b < BINS; ++b) rows[b][tid] = make_float2(0.0f, 0.0f);

    const int n4      = n >> 2;
    const int stride4 = GRID * BLOCK;
    const int idx     = blockIdx.x * BLOCK + tid;
    const int per_it  = 4 * stride4;          // float4-groups per super-iteration
    const int full    = n4 / per_it;          // fully-valid super-iterations (uniform)
    const float4* __restrict__ x4 = (const float4*)x;
    const int4*   __restrict__ t4 = (const int4*)tg;

    // Hot loop: 16 elems/thread/iter, 8 front-batched LDG.128, zero validity logic.
    for (int it = 0; it < full; ++it) {
        const int base = idx + it * per_it;
        float4 xv[4]; int4 tv[4];
        #pragma unroll
        for (int k = 0; k < 4; ++k) {
            xv[k] = x4[base + k * stride4];
            tv[k] = t4[base + k * stride4];
        }
        #pragma unroll
        for (int k = 0; k < 4; ++k) {
            ghm_elem(xv[k].x, tv[k].x, rowbase);
            ghm_elem(xv[k].y, tv[k].y, rowbase);
            ghm_elem(xv[k].z, tv[k].z, rowbase);
            ghm_elem(xv[k].w, tv[k].w, rowbase);
        }
    }

    // Ragged float4 tail.
    for (int i = idx + full * per_it; i < n4; i += stride4) {
        const float4 xv = x4[i];
        const int4   tv = t4[i];
        ghm_elem(xv.x, tv.x, rowbase);
        ghm_elem(xv.y, tv.y, rowbase);
        ghm_elem(xv.z, tv.z, rowbase);
        ghm_elem(xv.w, tv.w, rowbase);
    }

    // Scalar tail (n % 4), block 0 only.
    if (blockIdx.x == 0 && tid < (n & 3)) {
        const int i = (n & ~3) + tid;
        ghm_elem(x[i], tg[i], rowbase);
    }

    // ── Reduction: own smem column -> regs -> warp butterfly -> block -> global ──
    float sums[BINS], cnts[BINS];
    #pragma unroll
    for (int b = 0; b < BINS; ++b) {
        const float2 v = rows[b][tid];     // own cells only; no sync needed
        sums[b] = v.x; cnts[b] = v.y;
    }
    #pragma unroll
    for (int b = 0; b < BINS; ++b) {
        #pragma unroll
        for (int o = 16; o; o >>= 1) {
            sums[b] += __shfl_xor_sync(0xffffffffu, sums[b], o);
            cnts[b] += __shfl_xor_sync(0xffffffffu, cnts[b], o);
        }
    }
    if (tid < 2 * BINS) sh_fin[tid] = 0.0f;
    __syncthreads();
    if ((tid & 31) == 0) {
        #pragma unroll
        for (int b = 0; b < BINS; ++b) {
            atomicAdd(&sh_fin[b], sums[b]);
            atomicAdd(&sh_fin[BINS + b], cnts[b]);
        }
    }
    __syncthreads();
    if (tid < BINS) {
        atomicAdd(&g_sum[tid], sh_fin[tid]);
        atomicAdd(&g_cnt[tid], sh_fin[BINS + tid]);
    }

    // Last-block ticket: finalize + reset scratch for next graph replay.
    __threadfence();
    if (tid == 0) {
        const unsigned t = atomicAdd(&g_ticket, 1u);
        s_last = (t == (unsigned)(GRID - 1));
    }
    __syncthreads();
    if (s_last && tid < 32) {
        float c = 0.0f, ssum = 0.0f;
        if (tid < BINS) {
            c    = atomicAdd(&g_cnt[tid], 0.0f);   // coherent L2 read
            ssum = atomicAdd(&g_sum[tid], 0.0f);
        }
        const unsigned ne = __ballot_sync(0xffffffffu, (tid < BINS) && (c > 0.0f));
        const float nonempty = (float)__popc(ne);
        float term = 0.0f;
        if (tid < BINS)
            term = (LN2 * ssum) / fmaxf(c * nonempty, 1e-6f);  // deferred ln2 scale
        #pragma unroll
        for (int o = 16; o; o >>= 1)
            term += __shfl_xor_sync(0xffffffffu, term, o);
        for (int i = tid; i < out_size; i += 32) out[i] = term;
        if (tid < BINS) { g_sum[tid] = 0.0f; g_cnt[tid] = 0.0f; }
        if (tid == 0) g_ticket = 0u;
    }
}

extern "C" void kernel_launch(void* const* d_in, const int* in_sizes, int n_in,
                              void* d_out, int out_size) {
    const float* x = (const float*)d_in[0];
    const int*   t = (const int*)d_in[1];
    const int n = in_sizes[0];
    ghm_fused<<<GRID, BLOCK>>>(x, t, n, (float*)d_out, out_size);
}